// round 5
// baseline (speedup 1.0000x reference)
#include <cuda_runtime.h>

#define N_ROWS 32768
#define F_IN   1024
#define F_OUT  512

// ---------------- device scratch (no allocations allowed) ----------------
__device__ double g_w1d[F_IN];         // W @ a1 (double)
__device__ float  g_w2hi[F_IN];        // W @ a2 hi part
__device__ float  g_w2lo[F_IN];        // W @ a2 lo part (double - hi)
__device__ double g_s0d;               // h . (W @ a1)
__device__ double g_scored[N_ROWS];    // near-exact scores
__device__ float  g_e[N_ROWS];         // exp(score - max), fp32 (for v pass)
__device__ float  g_v[F_IN];           // sum_i e_i * adj[i]  (unnormalized)
__device__ float  g_invZ;
__device__ double g_T;                 // score-space threshold: max + ln(Z) - ln(N)

// ---------------- helpers ----------------
__device__ __forceinline__ float warp_sum_f(float x) {
    #pragma unroll
    for (int off = 16; off > 0; off >>= 1)
        x += __shfl_down_sync(0xffffffffu, x, off);
    return x;
}
__device__ __forceinline__ double warp_sum_d(double x) {
    #pragma unroll
    for (int off = 16; off > 0; off >>= 1)
        x += __shfl_down_sync(0xffffffffu, x, off);
    return x;
}
__device__ __forceinline__ double warp_max_d(double x) {
    #pragma unroll
    for (int off = 16; off > 0; off >>= 1)
        x = fmax(x, __shfl_down_sync(0xffffffffu, x, off));
    return x;
}

// TwoSum merge of compensated pairs (x = sum, y = compensation).
// No muls -> no contraction risk; use explicit rn intrinsics anyway.
__device__ __forceinline__ float2 ts_merge(float2 A, float2 B) {
    float s  = __fadd_rn(A.x, B.x);
    float bv = __fsub_rn(s, A.x);
    float av = __fsub_rn(s, bv);
    float e  = __fadd_rn(__fsub_rn(A.x, av), __fsub_rn(B.x, bv));
    return make_float2(s, __fadd_rn(__fadd_rn(A.y, B.y), e));
}
// Add product v*whi (+ v*wlo correction) into compensated accumulator.
__device__ __forceinline__ float2 ts_addprod(float2 acc, float v, float whi, float wlo) {
    float p  = __fmul_rn(v, whi);
    float pe = __fmaf_rn(v, whi, -p);      // exact product error
    pe = __fmaf_rn(v, wlo, pe);            // low part of w2
    return ts_merge(acc, make_float2(p, pe));
}

// ---------------- K0: zero the v accumulator ----------------
__global__ void k_zero_v() {
    int i = blockIdx.x * blockDim.x + threadIdx.x;
    if (i < F_IN) g_v[i] = 0.0f;
}

// ---------------- K1: w1 = W@a1, w2 = W@a2 in double (tiny) -------------
__global__ void k_w12(const float* __restrict__ W, const float* __restrict__ a) {
    const int j   = blockIdx.x;        // 0..F_IN-1
    const int tid = threadIdx.x;       // 128 threads
    const float* __restrict__ row = W + (size_t)j * F_OUT;
    double p1 = 0.0, p2 = 0.0;
    for (int k = tid; k < F_OUT; k += 128) {
        double w = (double)row[k];
        p1 += w * (double)__ldg(a + k);
        p2 += w * (double)__ldg(a + F_OUT + k);
    }
    p1 = warp_sum_d(p1);
    p2 = warp_sum_d(p2);
    __shared__ double s1[4], s2[4];
    if ((tid & 31) == 0) { s1[tid >> 5] = p1; s2[tid >> 5] = p2; }
    __syncthreads();
    if (tid == 0) {
        double w1 = s1[0] + s1[1] + s1[2] + s1[3];
        double w2 = s2[0] + s2[1] + s2[2] + s2[3];
        g_w1d[j] = w1;
        float hi = (float)w2;
        g_w2hi[j] = hi;
        g_w2lo[j] = (float)(w2 - (double)hi);
    }
}

// ---------------- K1b: s0 = h . w1 (double) ----------------
__global__ void k_s0(const float* __restrict__ h) {
    const int tid = threadIdx.x;       // 256 threads, one block
    double p = 0.0;
    for (int j = tid; j < F_IN; j += 256) p += (double)h[j] * g_w1d[j];
    p = warp_sum_d(p);
    __shared__ double s[8];
    if ((tid & 31) == 0) s[tid >> 5] = p;
    __syncthreads();
    if (tid == 0) {
        double t = 0.0;
        #pragma unroll
        for (int w = 0; w < 8; w++) t += s[w];
        g_s0d = t;
    }
}

// ---------------- K2: scores_i = leaky_relu(s0 + adj[i].w2) -------------
// one block (256 thr) per row; compensated fp32 dot -> ~double accuracy
__global__ void k_scores(const float* __restrict__ adj) {
    const int row = blockIdx.x;
    const int tid = threadIdx.x;
    const float4 v  = reinterpret_cast<const float4*>(adj + (size_t)row * F_IN)[tid];
    const float4 wh = reinterpret_cast<const float4*>(g_w2hi)[tid];
    const float4 wl = reinterpret_cast<const float4*>(g_w2lo)[tid];

    float2 acc = make_float2(0.f, 0.f);
    acc = ts_addprod(acc, v.x, wh.x, wl.x);
    acc = ts_addprod(acc, v.y, wh.y, wl.y);
    acc = ts_addprod(acc, v.z, wh.z, wl.z);
    acc = ts_addprod(acc, v.w, wh.w, wl.w);

    #pragma unroll
    for (int off = 16; off > 0; off >>= 1) {
        float2 o;
        o.x = __shfl_down_sync(0xffffffffu, acc.x, off);
        o.y = __shfl_down_sync(0xffffffffu, acc.y, off);
        acc = ts_merge(acc, o);
    }
    __shared__ float2 s8[8];
    if ((tid & 31) == 0) s8[tid >> 5] = acc;
    __syncthreads();
    if (tid < 32) {
        float2 a2 = (tid < 8) ? s8[tid] : make_float2(0.f, 0.f);
        #pragma unroll
        for (int off = 4; off > 0; off >>= 1) {
            float2 o;
            o.x = __shfl_down_sync(0xffffffffu, a2.x, off);
            o.y = __shfl_down_sync(0xffffffffu, a2.y, off);
            a2 = ts_merge(a2, o);
        }
        if (tid == 0) {
            double sc = (double)a2.x + (double)a2.y + g_s0d;
            const double alpha = (double)0.1f;      // jax fp32 literal
            g_scored[row] = sc > 0.0 ? sc : alpha * sc;
        }
    }
}

// ---------------- K3: softmax stats (single block, 1024 thr) ------------
__global__ void k_softmax_stats() {
    const int tid = threadIdx.x;
    __shared__ double shd[32];
    __shared__ double s_bcast;

    // ---- max (double) ----
    double m = -1.0e300;
    for (int i = tid; i < N_ROWS; i += 1024) m = fmax(m, g_scored[i]);
    m = warp_max_d(m);
    if ((tid & 31) == 0) shd[tid >> 5] = m;
    __syncthreads();
    if (tid < 32) {
        double t = shd[tid];
        t = warp_max_d(t);
        if (tid == 0) s_bcast = t;
    }
    __syncthreads();
    m = s_bcast;
    __syncthreads();

    // ---- e (fp32) + Z (double) ----
    double sum = 0.0;
    for (int i = tid; i < N_ROWS; i += 1024) {
        float e = expf((float)(g_scored[i] - m));
        g_e[i] = e;
        sum += (double)e;
    }
    sum = warp_sum_d(sum);
    if ((tid & 31) == 0) shd[tid >> 5] = sum;
    __syncthreads();
    if (tid < 32) {
        double t = shd[tid];
        t = warp_sum_d(t);
        if (tid == 0) {
            double Z = t;
            g_invZ = (float)(1.0 / Z);
            // att_i > mean  <=>  e_i/Z > 1/N  <=>  s_i > m + ln(Z) - ln(N)
            g_T = m + log(Z) - log((double)N_ROWS);
        }
    }
}

// ---------------- K4: v = sum_i e_i * adj[i]  (+ attention2 writes) -----
#define RPB 16
__global__ void k_accum_v(const float* __restrict__ adj,
                          float* __restrict__ att2, int write_att2) {
    const int tid  = threadIdx.x;            // 256 threads -> 1024 cols via float4
    const int base = blockIdx.x * RPB;
    float4 acc = make_float4(0.f, 0.f, 0.f, 0.f);
    #pragma unroll 4
    for (int r = 0; r < RPB; r++) {
        const int row = base + r;
        const float e = g_e[row];
        const float4 v = reinterpret_cast<const float4*>(
            adj + (size_t)row * F_IN)[tid];
        acc.x += e * v.x;
        acc.y += e * v.y;
        acc.z += e * v.z;
        acc.w += e * v.w;
    }
    float* vp = g_v + tid * 4;
    atomicAdd(vp + 0, acc.x);
    atomicAdd(vp + 1, acc.y);
    atomicAdd(vp + 2, acc.z);
    atomicAdd(vp + 3, acc.w);

    if (write_att2 && tid < RPB) {
        const int row = base + tid;
        att2[row] = (g_scored[row] > g_T) ? 1.0f : 0.0f;
    }
}

// ---------------- K5: out[k] = invZ * sum_j v[j] * W1[j,k] --------------
__global__ void k_out(const float* __restrict__ W1, float* __restrict__ out) {
    const int k = blockIdx.x * blockDim.x + threadIdx.x;  // 512 total
    if (k >= F_OUT) return;
    float acc = 0.f;
    #pragma unroll 8
    for (int j = 0; j < F_IN; j++)
        acc += g_v[j] * W1[(size_t)j * F_OUT + k];
    out[k] = acc * g_invZ;
}

// ---------------- launch ----------------
extern "C" void kernel_launch(void* const* d_in, const int* in_sizes, int n_in,
                              void* d_out, int out_size) {
    const float* h   = (const float*)d_in[0];
    const float* adj = (const float*)d_in[1];
    const float* W   = (const float*)d_in[2];
    const float* a   = (const float*)d_in[3];
    const float* W1  = (const float*)d_in[4];
    float* out = (float*)d_out;

    // Output layout (confirmed by R4 error report: both outputs compared):
    //   >= 33280 : [out(512) | attention2(32768)]
    //   == 512   : out only
    //   == 32768 : attention2 only
    bool  want_out = true;
    float* att2    = nullptr;
    if (out_size >= F_OUT + N_ROWS) {
        att2 = out + F_OUT;
    } else if (out_size == N_ROWS) {
        att2 = out;
        want_out = false;
    }

    k_zero_v<<<(F_IN + 255) / 256, 256>>>();
    k_w12<<<F_IN, 128>>>(W, a);
    k_s0<<<1, 256>>>(h);
    k_scores<<<N_ROWS, 256>>>(adj);
    k_softmax_stats<<<1, 1024>>>();
    k_accum_v<<<N_ROWS / RPB, 256>>>(adj, att2, att2 != nullptr ? 1 : 0);
    if (want_out) k_out<<<(F_OUT + 127) / 128, 128>>>(W1, out);
}

// round 6
// speedup vs baseline: 3.3648x; 3.3648x over previous
#include <cuda_runtime.h>

#define N_ROWS 32768
#define F_IN   1024
#define F_OUT  512

// ---------------- device scratch (no allocations allowed) ----------------
__device__ float  g_w2hi[F_IN];        // W @ a2 hi part
__device__ float  g_w2lo[F_IN];        // W @ a2 lo part (double - hi)
__device__ double g_s0d;               // h . (W @ a1)        (atomic accum)
__device__ double g_sumpos;            // sum_j max(0, W@a2)  (atomic accum)
__device__ double g_scored[N_ROWS];    // near-exact scores
__device__ double g_Z;                 // sum_i exp(s_i - C)  (atomic accum)
__device__ float  g_v[F_IN];           // sum_i e_i * adj[i]  (unnormalized)
__device__ float  g_invZ;
__device__ double g_T;                 // score-space threshold

// ---------------- helpers ----------------
__device__ __forceinline__ double warp_sum_d(double x) {
    #pragma unroll
    for (int off = 16; off > 0; off >>= 1)
        x += __shfl_down_sync(0xffffffffu, x, off);
    return x;
}

// TwoSum merge of compensated pairs (x = sum, y = compensation).
__device__ __forceinline__ float2 ts_merge(float2 A, float2 B) {
    float s  = __fadd_rn(A.x, B.x);
    float bv = __fsub_rn(s, A.x);
    float av = __fsub_rn(s, bv);
    float e  = __fadd_rn(__fsub_rn(A.x, av), __fsub_rn(B.x, bv));
    return make_float2(s, __fadd_rn(__fadd_rn(A.y, B.y), e));
}
// Add product v*whi (+ v*wlo correction) into compensated accumulator.
__device__ __forceinline__ float2 ts_addprod(float2 acc, float v, float whi, float wlo) {
    float p  = __fmul_rn(v, whi);
    float pe = __fmaf_rn(v, whi, -p);      // exact product error
    pe = __fmaf_rn(v, wlo, pe);            // low part of w2
    return ts_merge(acc, make_float2(p, pe));
}

// ---------------- K_init: zero accumulators (+ out if used) -------------
__global__ void k_init(float* out, int zero_out) {
    const int tid = threadIdx.x;           // 1024 threads, one block
    g_v[tid] = 0.0f;
    if (zero_out && tid < F_OUT) out[tid] = 0.0f;
    if (tid == 0) { g_s0d = 0.0; g_sumpos = 0.0; g_Z = 0.0; }
}

// ---------------- K1: w2 hi/lo, s0 (atomic), sumpos (atomic) ------------
__global__ void k_w12(const float* __restrict__ W, const float* __restrict__ a,
                      const float* __restrict__ h) {
    const int j   = blockIdx.x;            // 0..F_IN-1
    const int tid = threadIdx.x;           // 128 threads
    const float* __restrict__ row = W + (size_t)j * F_OUT;
    double p1 = 0.0, p2 = 0.0;
    for (int k = tid; k < F_OUT; k += 128) {
        double w = (double)row[k];
        p1 += w * (double)__ldg(a + k);
        p2 += w * (double)__ldg(a + F_OUT + k);
    }
    p1 = warp_sum_d(p1);
    p2 = warp_sum_d(p2);
    __shared__ double s1[4], s2[4];
    if ((tid & 31) == 0) { s1[tid >> 5] = p1; s2[tid >> 5] = p2; }
    __syncthreads();
    if (tid == 0) {
        double w1 = s1[0] + s1[1] + s1[2] + s1[3];
        double w2 = s2[0] + s2[1] + s2[2] + s2[3];
        float hi = (float)w2;
        g_w2hi[j] = hi;
        g_w2lo[j] = (float)(w2 - (double)hi);
        atomicAdd(&g_s0d, w1 * (double)h[j]);
        atomicAdd(&g_sumpos, w2 > 0.0 ? w2 : 0.0);
    }
}

// ---------------- K2 (fused): scores + e + v-accum + Z, ONE adj pass ----
// 256 thr = 8 warps; warp handles 8 rows (entire 1024-wide row per warp).
// Lane l, chunk u -> float4 index u*32+l (coalesced).
__global__ void __launch_bounds__(256) k_fused(const float* __restrict__ adj) {
    __shared__ float4 sh_wh[256], sh_wl[256];
    __shared__ float  sh_v[F_IN];
    __shared__ double sh_z[8];
    const int tid  = threadIdx.x;
    const int wid  = tid >> 5;
    const int lane = tid & 31;

    sh_wh[tid] = reinterpret_cast<const float4*>(g_w2hi)[tid];
    sh_wl[tid] = reinterpret_cast<const float4*>(g_w2lo)[tid];
    sh_v[tid]         = 0.0f;
    sh_v[tid + 256]   = 0.0f;
    sh_v[tid + 512]   = 0.0f;
    sh_v[tid + 768]   = 0.0f;
    __syncthreads();

    const double s0 = g_s0d;
    const double Cd = s0 + g_sumpos;       // upper bound on scores (adj in [0,1))

    float4 vacc[8];
    #pragma unroll
    for (int u = 0; u < 8; u++) vacc[u] = make_float4(0.f, 0.f, 0.f, 0.f);
    double zsum = 0.0;

    const int row0 = blockIdx.x * 64 + wid * 8;
    for (int r = 0; r < 8; r++) {
        const int row = row0 + r;
        const float4* __restrict__ vp =
            reinterpret_cast<const float4*>(adj + (size_t)row * F_IN);
        float4 v[8];
        #pragma unroll
        for (int u = 0; u < 8; u++) v[u] = vp[u * 32 + lane];

        float2 acc = make_float2(0.f, 0.f);
        #pragma unroll
        for (int u = 0; u < 8; u++) {
            const float4 wh = sh_wh[u * 32 + lane];
            const float4 wl = sh_wl[u * 32 + lane];
            acc = ts_addprod(acc, v[u].x, wh.x, wl.x);
            acc = ts_addprod(acc, v[u].y, wh.y, wl.y);
            acc = ts_addprod(acc, v[u].z, wh.z, wl.z);
            acc = ts_addprod(acc, v[u].w, wh.w, wl.w);
        }
        // exact-ish collapse to double, then exact double tree-reduce
        double d = (double)acc.x + (double)acc.y;
        #pragma unroll
        for (int off = 16; off > 0; off >>= 1)
            d += __shfl_down_sync(0xffffffffu, d, off);

        float e;
        if (lane == 0) {
            double sc = d + s0;
            const double alpha = (double)0.1f;   // jax fp32 literal
            sc = sc > 0.0 ? sc : alpha * sc;
            g_scored[row] = sc;
            e = expf((float)(sc - Cd));
            zsum += (double)e;
        }
        e = __shfl_sync(0xffffffffu, e, 0);

        #pragma unroll
        for (int u = 0; u < 8; u++) {
            vacc[u].x = __fmaf_rn(e, v[u].x, vacc[u].x);
            vacc[u].y = __fmaf_rn(e, v[u].y, vacc[u].y);
            vacc[u].z = __fmaf_rn(e, v[u].z, vacc[u].z);
            vacc[u].w = __fmaf_rn(e, v[u].w, vacc[u].w);
        }
    }

    if (lane == 0) sh_z[wid] = zsum;

    // per-warp v partials -> shared (column index = (u*32+lane)*4 + c)
    #pragma unroll
    for (int u = 0; u < 8; u++) {
        const int base = (u * 32 + lane) * 4;
        atomicAdd(&sh_v[base + 0], vacc[u].x);
        atomicAdd(&sh_v[base + 1], vacc[u].y);
        atomicAdd(&sh_v[base + 2], vacc[u].z);
        atomicAdd(&sh_v[base + 3], vacc[u].w);
    }
    __syncthreads();

    if (tid == 0) {
        double z = 0.0;
        #pragma unroll
        for (int w = 0; w < 8; w++) z += sh_z[w];
        atomicAdd(&g_Z, z);
    }
    const float4 sv = reinterpret_cast<const float4*>(sh_v)[tid];
    atomicAdd(&g_v[tid * 4 + 0], sv.x);
    atomicAdd(&g_v[tid * 4 + 1], sv.y);
    atomicAdd(&g_v[tid * 4 + 2], sv.z);
    atomicAdd(&g_v[tid * 4 + 3], sv.w);
}

// ---------------- K3: finalize scalars ----------------
__global__ void k_finalize() {
    const double Z = g_Z;
    g_invZ = (float)(1.0 / Z);
    // att_i > 1/N  <=>  s_i - C > ln Z - ln N
    g_T = (g_s0d + g_sumpos) + log(Z) - log((double)N_ROWS);
}

// ---------------- K4: attention2 mask ----------------
__global__ void k_att2(float* __restrict__ att2) {
    const int i = blockIdx.x * 256 + threadIdx.x;
    att2[i] = (g_scored[i] > g_T) ? 1.0f : 0.0f;
}

// ---------------- K5: out[k] = invZ * sum_j v[j] * W1[j,k] --------------
// 64 blocks x 512 threads; block b covers j in [16b, 16b+16).
__global__ void k_out(const float* __restrict__ W1, float* __restrict__ out) {
    const int k  = threadIdx.x;            // 0..511
    const int j0 = blockIdx.x * 16;
    float acc = 0.f;
    #pragma unroll
    for (int j = 0; j < 16; j++)
        acc = __fmaf_rn(g_v[j0 + j], W1[(size_t)(j0 + j) * F_OUT + k], acc);
    atomicAdd(&out[k], acc * g_invZ);
}

// ---------------- launch ----------------
extern "C" void kernel_launch(void* const* d_in, const int* in_sizes, int n_in,
                              void* d_out, int out_size) {
    const float* h   = (const float*)d_in[0];
    const float* adj = (const float*)d_in[1];
    const float* W   = (const float*)d_in[2];
    const float* a   = (const float*)d_in[3];
    const float* W1  = (const float*)d_in[4];
    float* out = (float*)d_out;

    // Output layout (confirmed passing in R5):
    //   >= 33280 : [out(512) | attention2(32768)]
    //   == 512   : out only
    //   == 32768 : attention2 only
    bool  want_out = true;
    float* att2    = nullptr;
    if (out_size >= F_OUT + N_ROWS) {
        att2 = out + F_OUT;
    } else if (out_size == N_ROWS) {
        att2 = out;
        want_out = false;
    }

    k_init<<<1, 1024>>>(out, want_out ? 1 : 0);
    k_w12<<<F_IN, 128>>>(W, a, h);
    k_fused<<<N_ROWS / 64, 256>>>(adj);
    k_finalize<<<1, 1>>>();
    if (att2) k_att2<<<N_ROWS / 256, 256>>>(att2);
    if (want_out) k_out<<<F_IN / 16, F_OUT>>>(W1, out);
}